// round 1
// baseline (speedup 1.0000x reference)
#include <cuda_runtime.h>
#include <math.h>

// Problem constants
#define NT   1024          // tokens
#define ND   2048          // hidden dim
#define NE   32            // experts
#define NI   1408          // routed intermediate
#define NSI  2816          // shared intermediate
#define NG   8             // groups
#define EPG  4             // experts per group
#define NA   (NT * 4)      // total assignments (top_k = 4, exact)

// ---------------- device scratch (no allocation allowed) ----------------
__device__ float g_h [NA * NI];    // routed  silu(x@Wg)*(x@Wu)   23 MB
__device__ float g_hs[NT * NSI];   // shared  silu(x@Sg)*(x@Su)   11.5 MB
__device__ int   g_rowlist[NA];    // assignment row -> token id (grouped by expert)
__device__ float g_roww  [NA];     // assignment row -> combine weight
__device__ int   g_counts [NE];
__device__ int   g_offsets[NE];
__device__ int   g_cursor [NE];
__device__ int   g_tid4[NA];       // per-token top-4 expert ids
__device__ float g_tw4 [NA];       // per-token top-4 weights (normalized)

// ---------------- tiny kernels ----------------
__global__ void zero_kernel() {
    int i = threadIdx.x;
    if (i < NE) { g_counts[i] = 0; g_cursor[i] = 0; }
}

// One block per token: logits = x@gate_w^T + gate_b ; sigmoid ; biased grouped top-k.
__global__ void gate_kernel(const float* __restrict__ x,
                            const float* __restrict__ gw,
                            const float* __restrict__ gb) {
    __shared__ float xs[ND];
    __shared__ float logit[NE];
    int t = blockIdx.x;
    for (int k = threadIdx.x; k < ND; k += 256) xs[k] = x[(size_t)t * ND + k];
    __syncthreads();

    int e = threadIdx.x >> 3;         // 32 experts x 8 threads
    int j = threadIdx.x & 7;
    const float* w = gw + (size_t)e * ND;
    float s = 0.f;
    for (int k = j; k < ND; k += 8) s += xs[k] * w[k];
    s += __shfl_xor_sync(0xffffffffu, s, 1);
    s += __shfl_xor_sync(0xffffffffu, s, 2);
    s += __shfl_xor_sync(0xffffffffu, s, 4);
    if (j == 0) logit[e] = s + gb[e];
    __syncthreads();

    if (threadIdx.x == 0) {
        float sc[NE], scb[NE];
        #pragma unroll
        for (int i = 0; i < NE; i++) {
            float v = 1.f / (1.f + expf(-logit[i]));
            sc[i]  = v;             // unbiased sigmoid (used for weights)
            scb[i] = v + gb[i];     // biased score (used for choice) — bias applied twice, per reference
        }
        // group score = sum of top-2 biased scores in each group of 4
        float gs[NG];
        #pragma unroll
        for (int g = 0; g < NG; g++) {
            float m1 = -1e30f, m2 = -1e30f;
            #pragma unroll
            for (int q = 0; q < EPG; q++) {
                float v = scb[g * EPG + q];
                if (v > m1) { m2 = m1; m1 = v; } else if (v > m2) { m2 = v; }
            }
            gs[g] = m1 + m2;
        }
        // top-4 groups (strict '>' scan in ascending index order == lax.top_k tie rule)
        bool gsel[NG];
        #pragma unroll
        for (int g = 0; g < NG; g++) gsel[g] = false;
        for (int r = 0; r < 4; r++) {
            float best = -1e30f; int bi = 0;
            for (int g = 0; g < NG; g++)
                if (!gsel[g] && gs[g] > best) { best = gs[g]; bi = g; }
            gsel[bi] = true;
        }
        // masked scores: exactly jnp.where(mask, scb, 0.0) — masked entries become 0.0
        float tmp[NE];
        #pragma unroll
        for (int i = 0; i < NE; i++) tmp[i] = gsel[i / EPG] ? scb[i] : 0.0f;
        // top-4 experts of tmp
        int ids[4]; float tw[4]; float wsum = 0.f;
        for (int r = 0; r < 4; r++) {
            float best = -1e30f; int bi = 0;
            for (int i = 0; i < NE; i++)
                if (tmp[i] > best) { best = tmp[i]; bi = i; }
            tmp[bi] = -1e30f;
            ids[r] = bi;
            tw[r] = sc[bi];           // weights from UNbiased sigmoid scores
            wsum += tw[r];
        }
        float inv = 1.f / wsum;
        for (int r = 0; r < 4; r++) {
            g_tid4[t * 4 + r] = ids[r];
            g_tw4 [t * 4 + r] = tw[r] * inv;
            atomicAdd(&g_counts[ids[r]], 1);
        }
    }
}

__global__ void scan_kernel() {   // 32 threads: exclusive scan of counts
    int tid = threadIdx.x;
    int c = g_counts[tid];
    int v = c;
    #pragma unroll
    for (int o = 1; o < 32; o <<= 1) {
        int u = __shfl_up_sync(0xffffffffu, v, o);
        if (tid >= o) v += u;
    }
    g_offsets[tid] = v - c;
}

__global__ void scatter_kernel() {
    int i = blockIdx.x * blockDim.x + threadIdx.x;
    if (i >= NA) return;
    int t = i >> 2;
    int e = g_tid4[i];
    int pos = atomicAdd(&g_cursor[e], 1);
    int row = g_offsets[e] + pos;
    g_rowlist[row] = t;
    g_roww[row]   = g_tw4[i];
}

// ---------------- GEMM 1: H = silu(A@Wg) * (A@Wu) ----------------
// BM=128, BN=64, BK=16, 256 threads, 8x4 per-thread tile, dual accumulators.
template<int IDIM, bool GATHER>
__global__ void __launch_bounds__(256, 2)
gemm_gated(const float* __restrict__ x,
           const float* __restrict__ Wg,
           const float* __restrict__ Wu) {
    int e   = GATHER ? blockIdx.z : 0;
    int cnt = GATHER ? g_counts[e]  : NT;
    int off = GATHER ? g_offsets[e] : 0;
    int m0  = blockIdx.x * 128;
    if (m0 >= cnt) return;
    int n0  = blockIdx.y * 64;
    const float* wg = Wg + (size_t)e * ND * IDIM;
    const float* wu = Wu + (size_t)e * ND * IDIM;
    float* H = GATHER ? g_h : g_hs;

    __shared__ float As[16][132];   // transposed A tile, padded
    __shared__ float Bg[16][68];
    __shared__ float Bu[16][68];

    int tid = threadIdx.x;
    int tx = tid & 15, ty = tid >> 4;

    // A-tile loader mapping: two float4 per thread
    const float* aptr[2];
    int mA[2], kA[2];
    #pragma unroll
    for (int l = 0; l < 2; l++) {
        int idx = tid + l * 256;
        mA[l] = idx >> 2; kA[l] = (idx & 3) << 2;
        int m = m0 + mA[l];
        int tok;
        if (GATHER) tok = (m < cnt) ? g_rowlist[off + m] : 0;
        else        tok = (m < cnt) ? m : 0;
        aptr[l] = x + (size_t)tok * ND + kA[l];
    }
    // B-tile loader: one float4 per thread per matrix
    int kB = tid >> 4, nB = (tid & 15) << 2;
    const float* bgp = wg + (size_t)kB * IDIM + n0 + nB;
    const float* bup = wu + (size_t)kB * IDIM + n0 + nB;

    float accg[8][4], accu[8][4];
    #pragma unroll
    for (int r = 0; r < 8; r++)
        #pragma unroll
        for (int c = 0; c < 4; c++) { accg[r][c] = 0.f; accu[r][c] = 0.f; }

    float4 ra0 = *(const float4*)(aptr[0]);
    float4 ra1 = *(const float4*)(aptr[1]);
    float4 rbg = *(const float4*)(bgp);
    float4 rbu = *(const float4*)(bup);

    for (int kt = 0; kt < ND; kt += 16) {
        As[kA[0]+0][mA[0]] = ra0.x; As[kA[0]+1][mA[0]] = ra0.y;
        As[kA[0]+2][mA[0]] = ra0.z; As[kA[0]+3][mA[0]] = ra0.w;
        As[kA[1]+0][mA[1]] = ra1.x; As[kA[1]+1][mA[1]] = ra1.y;
        As[kA[1]+2][mA[1]] = ra1.z; As[kA[1]+3][mA[1]] = ra1.w;
        *(float4*)&Bg[kB][nB] = rbg;
        *(float4*)&Bu[kB][nB] = rbu;
        __syncthreads();
        if (kt + 16 < ND) {
            ra0 = *(const float4*)(aptr[0] + kt + 16);
            ra1 = *(const float4*)(aptr[1] + kt + 16);
            rbg = *(const float4*)(bgp + (size_t)(kt + 16) * IDIM);
            rbu = *(const float4*)(bup + (size_t)(kt + 16) * IDIM);
        }
        #pragma unroll
        for (int kk = 0; kk < 16; kk++) {
            float a[8];
            *(float4*)&a[0] = *(const float4*)&As[kk][ty * 8];
            *(float4*)&a[4] = *(const float4*)&As[kk][ty * 8 + 4];
            float4 b0 = *(const float4*)&Bg[kk][tx * 4];
            float4 b1 = *(const float4*)&Bu[kk][tx * 4];
            float bg4[4] = {b0.x, b0.y, b0.z, b0.w};
            float bu4[4] = {b1.x, b1.y, b1.z, b1.w};
            #pragma unroll
            for (int r = 0; r < 8; r++)
                #pragma unroll
                for (int c = 0; c < 4; c++) {
                    accg[r][c] = fmaf(a[r], bg4[c], accg[r][c]);
                    accu[r][c] = fmaf(a[r], bu4[c], accu[r][c]);
                }
        }
        __syncthreads();
    }
    // epilogue: silu(gate) * up
    #pragma unroll
    for (int r = 0; r < 8; r++) {
        int m = m0 + ty * 8 + r;
        if (m >= cnt) continue;
        float* hp = H + (size_t)(off + m) * IDIM + n0 + tx * 4;
        float4 hv;
        {
            float g0 = accg[r][0], g1 = accg[r][1], g2 = accg[r][2], g3 = accg[r][3];
            hv.x = g0 / (1.f + expf(-g0)) * accu[r][0];
            hv.y = g1 / (1.f + expf(-g1)) * accu[r][1];
            hv.z = g2 / (1.f + expf(-g2)) * accu[r][2];
            hv.w = g3 / (1.f + expf(-g3)) * accu[r][3];
        }
        *(float4*)hp = hv;
    }
}

// ---------------- GEMM 2: out (+)= H @ Wd  ----------------
template<int IDIM, bool ROUTED>
__global__ void __launch_bounds__(256, 2)
gemm_down(const float* __restrict__ Wd,
          float* __restrict__ out) {
    int e   = ROUTED ? blockIdx.z : 0;
    int cnt = ROUTED ? g_counts[e]  : NT;
    int off = ROUTED ? g_offsets[e] : 0;
    int m0  = blockIdx.x * 128;
    if (m0 >= cnt) return;
    int n0  = blockIdx.y * 64;
    const float* wd = Wd + (size_t)e * IDIM * ND;
    const float* H  = ROUTED ? g_h : g_hs;

    __shared__ float As[16][132];
    __shared__ float Bs[16][68];

    int tid = threadIdx.x;
    int tx = tid & 15, ty = tid >> 4;

    const float* aptr[2];
    int mA[2], kA[2];
    #pragma unroll
    for (int l = 0; l < 2; l++) {
        int idx = tid + l * 256;
        mA[l] = idx >> 2; kA[l] = (idx & 3) << 2;
        int m = m0 + mA[l];
        int hr = (m < cnt) ? (off + m) : off;  // clamp to valid row (result discarded)
        aptr[l] = H + (size_t)hr * IDIM + kA[l];
    }
    int kB = tid >> 4, nB = (tid & 15) << 2;
    const float* bp = wd + (size_t)kB * ND + n0 + nB;

    float acc[8][4];
    #pragma unroll
    for (int r = 0; r < 8; r++)
        #pragma unroll
        for (int c = 0; c < 4; c++) acc[r][c] = 0.f;

    float4 ra0 = *(const float4*)(aptr[0]);
    float4 ra1 = *(const float4*)(aptr[1]);
    float4 rb  = *(const float4*)(bp);

    for (int kt = 0; kt < IDIM; kt += 16) {
        As[kA[0]+0][mA[0]] = ra0.x; As[kA[0]+1][mA[0]] = ra0.y;
        As[kA[0]+2][mA[0]] = ra0.z; As[kA[0]+3][mA[0]] = ra0.w;
        As[kA[1]+0][mA[1]] = ra1.x; As[kA[1]+1][mA[1]] = ra1.y;
        As[kA[1]+2][mA[1]] = ra1.z; As[kA[1]+3][mA[1]] = ra1.w;
        *(float4*)&Bs[kB][nB] = rb;
        __syncthreads();
        if (kt + 16 < IDIM) {
            ra0 = *(const float4*)(aptr[0] + kt + 16);
            ra1 = *(const float4*)(aptr[1] + kt + 16);
            rb  = *(const float4*)(bp + (size_t)(kt + 16) * ND);
        }
        #pragma unroll
        for (int kk = 0; kk < 16; kk++) {
            float a[8];
            *(float4*)&a[0] = *(const float4*)&As[kk][ty * 8];
            *(float4*)&a[4] = *(const float4*)&As[kk][ty * 8 + 4];
            float4 b0 = *(const float4*)&Bs[kk][tx * 4];
            float b4[4] = {b0.x, b0.y, b0.z, b0.w};
            #pragma unroll
            for (int r = 0; r < 8; r++)
                #pragma unroll
                for (int c = 0; c < 4; c++)
                    acc[r][c] = fmaf(a[r], b4[c], acc[r][c]);
        }
        __syncthreads();
    }
    #pragma unroll
    for (int r = 0; r < 8; r++) {
        int m = m0 + ty * 8 + r;
        if (m >= cnt) continue;
        if (ROUTED) {
            int gr = off + m;
            int t  = g_rowlist[gr];
            float w = g_roww[gr] * 2.5f;   // routed scaling
            float* op = out + (size_t)t * ND + n0 + tx * 4;
            #pragma unroll
            for (int c = 0; c < 4; c++) atomicAdd(&op[c], w * acc[r][c]);
        } else {
            float* op = out + (size_t)m * ND + n0 + tx * 4;
            float4 v; v.x = acc[r][0]; v.y = acc[r][1]; v.z = acc[r][2]; v.w = acc[r][3];
            *(float4*)op = v;
        }
    }
}

// ---------------- launch ----------------
extern "C" void kernel_launch(void* const* d_in, const int* in_sizes, int n_in,
                              void* d_out, int out_size) {
    const float* x       = (const float*)d_in[0];
    const float* gate_w  = (const float*)d_in[1];
    const float* gate_b  = (const float*)d_in[2];
    const float* w_gate  = (const float*)d_in[3];
    const float* w_up    = (const float*)d_in[4];
    const float* w_down  = (const float*)d_in[5];
    const float* sw_gate = (const float*)d_in[6];
    const float* sw_up   = (const float*)d_in[7];
    const float* sw_down = (const float*)d_in[8];
    float* out = (float*)d_out;

    zero_kernel   <<<1, 32>>>();
    gate_kernel   <<<NT, 256>>>(x, gate_w, gate_b);
    scan_kernel   <<<1, 32>>>();
    scatter_kernel<<<NA / 256, 256>>>();

    // shared expert: gate/up then down (down WRITES out -> must precede routed atomics)
    gemm_gated<NSI, false><<<dim3(NT / 128, NSI / 64, 1), 256>>>(x, sw_gate, sw_up);
    // routed experts: gate/up (independent of shared, same stream keeps order)
    gemm_gated<NI,  true ><<<dim3(NT / 128, NI  / 64, NE), 256>>>(x, w_gate, w_up);
    // shared down-proj: plain stores initialize out
    gemm_down<NSI, false><<<dim3(NT / 128, ND / 64, 1), 256>>>(sw_down, out);
    // routed down-proj: weighted atomic accumulation into out
    gemm_down<NI,  true ><<<dim3(NT / 128, ND / 64, NE), 256>>>(w_down, out);
}

// round 2
// speedup vs baseline: 1.0033x; 1.0033x over previous
#include <cuda_runtime.h>
#include <math.h>

// Problem constants
#define NT   1024          // tokens
#define ND   2048          // hidden dim
#define NE   32            // experts
#define NI   1408          // routed intermediate
#define NSI  2816          // shared intermediate
#define NG   8             // groups
#define EPG  4             // experts per group
#define NA   (NT * 4)      // total assignments (top_k = 4, exact)

// ---------------- device scratch (no allocation allowed) ----------------
__device__ float g_h [NA * NI];    // routed  silu(x@Wg)*(x@Wu)   23 MB
__device__ float g_hs[NT * NSI];   // shared  silu(x@Sg)*(x@Su)   11.5 MB
__device__ int   g_rowlist[NA];    // assignment row -> token id (grouped by expert)
__device__ float g_roww  [NA];     // assignment row -> combine weight
__device__ int   g_counts [NE];
__device__ int   g_offsets[NE];
__device__ int   g_cursor [NE];
__device__ int   g_tid4[NA];       // per-token top-4 expert ids
__device__ float g_tw4 [NA];       // per-token top-4 weights (normalized)

// ---------------- tiny kernels ----------------
__global__ void zero_kernel() {
    int i = threadIdx.x;
    if (i < NE) { g_counts[i] = 0; g_cursor[i] = 0; }
}

// One block per token: logits = x@gate_w^T + gate_b ; sigmoid ; biased grouped top-k.
__global__ void gate_kernel(const float* __restrict__ x,
                            const float* __restrict__ gw,
                            const float* __restrict__ gb) {
    __shared__ float xs[ND];
    __shared__ float logit[NE];
    int t = blockIdx.x;
    for (int k = threadIdx.x; k < ND; k += 256) xs[k] = x[(size_t)t * ND + k];
    __syncthreads();

    int e = threadIdx.x >> 3;         // 32 experts x 8 threads
    int j = threadIdx.x & 7;
    const float* w = gw + (size_t)e * ND;
    float s = 0.f;
    for (int k = j; k < ND; k += 8) s += xs[k] * w[k];
    s += __shfl_xor_sync(0xffffffffu, s, 1);
    s += __shfl_xor_sync(0xffffffffu, s, 2);
    s += __shfl_xor_sync(0xffffffffu, s, 4);
    if (j == 0) logit[e] = s + gb[e];
    __syncthreads();

    if (threadIdx.x == 0) {
        float sc[NE], scb[NE];
        #pragma unroll
        for (int i = 0; i < NE; i++) {
            float v = 1.f / (1.f + expf(-logit[i]));
            sc[i]  = v;             // unbiased sigmoid (used for weights)
            scb[i] = v + gb[i];     // biased score (used for choice) — bias applied twice, per reference
        }
        // group score = sum of top-2 biased scores in each group of 4
        float gs[NG];
        #pragma unroll
        for (int g = 0; g < NG; g++) {
            float m1 = -1e30f, m2 = -1e30f;
            #pragma unroll
            for (int q = 0; q < EPG; q++) {
                float v = scb[g * EPG + q];
                if (v > m1) { m2 = m1; m1 = v; } else if (v > m2) { m2 = v; }
            }
            gs[g] = m1 + m2;
        }
        // top-4 groups (strict '>' scan in ascending index order == lax.top_k tie rule)
        bool gsel[NG];
        #pragma unroll
        for (int g = 0; g < NG; g++) gsel[g] = false;
        for (int r = 0; r < 4; r++) {
            float best = -1e30f; int bi = 0;
            for (int g = 0; g < NG; g++)
                if (!gsel[g] && gs[g] > best) { best = gs[g]; bi = g; }
            gsel[bi] = true;
        }
        // masked scores: exactly jnp.where(mask, scb, 0.0) — masked entries become 0.0
        float tmp[NE];
        #pragma unroll
        for (int i = 0; i < NE; i++) tmp[i] = gsel[i / EPG] ? scb[i] : 0.0f;
        // top-4 experts of tmp
        int ids[4]; float tw[4]; float wsum = 0.f;
        for (int r = 0; r < 4; r++) {
            float best = -1e30f; int bi = 0;
            for (int i = 0; i < NE; i++)
                if (tmp[i] > best) { best = tmp[i]; bi = i; }
            tmp[bi] = -1e30f;
            ids[r] = bi;
            tw[r] = sc[bi];           // weights from UNbiased sigmoid scores
            wsum += tw[r];
        }
        float inv = 1.f / wsum;
        for (int r = 0; r < 4; r++) {
            g_tid4[t * 4 + r] = ids[r];
            g_tw4 [t * 4 + r] = tw[r] * inv;
            atomicAdd(&g_counts[ids[r]], 1);
        }
    }
}

__global__ void scan_kernel() {   // 32 threads: exclusive scan of counts
    int tid = threadIdx.x;
    int c = g_counts[tid];
    int v = c;
    #pragma unroll
    for (int o = 1; o < 32; o <<= 1) {
        int u = __shfl_up_sync(0xffffffffu, v, o);
        if (tid >= o) v += u;
    }
    g_offsets[tid] = v - c;
}

__global__ void scatter_kernel() {
    int i = blockIdx.x * blockDim.x + threadIdx.x;
    if (i >= NA) return;
    int t = i >> 2;
    int e = g_tid4[i];
    int pos = atomicAdd(&g_cursor[e], 1);
    int row = g_offsets[e] + pos;
    g_rowlist[row] = t;
    g_roww[row]   = g_tw4[i];
}

// ---------------- GEMM 1: H = silu(A@Wg) * (A@Wu) ----------------
// BM=128, BN=64, BK=16, 256 threads, 8x4 per-thread tile, dual accumulators.
template<int IDIM, bool GATHER>
__global__ void __launch_bounds__(256, 2)
gemm_gated(const float* __restrict__ x,
           const float* __restrict__ Wg,
           const float* __restrict__ Wu) {
    int e   = GATHER ? blockIdx.z : 0;
    int cnt = GATHER ? g_counts[e]  : NT;
    int off = GATHER ? g_offsets[e] : 0;
    int m0  = blockIdx.x * 128;
    if (m0 >= cnt) return;
    int n0  = blockIdx.y * 64;
    const float* wg = Wg + (size_t)e * ND * IDIM;
    const float* wu = Wu + (size_t)e * ND * IDIM;
    float* H = GATHER ? g_h : g_hs;

    __shared__ float As[16][132];   // transposed A tile, padded
    __shared__ float Bg[16][68];
    __shared__ float Bu[16][68];

    int tid = threadIdx.x;
    int tx = tid & 15, ty = tid >> 4;

    // A-tile loader mapping: two float4 per thread
    const float* aptr[2];
    int mA[2], kA[2];
    #pragma unroll
    for (int l = 0; l < 2; l++) {
        int idx = tid + l * 256;
        mA[l] = idx >> 2; kA[l] = (idx & 3) << 2;
        int m = m0 + mA[l];
        int tok;
        if (GATHER) tok = (m < cnt) ? g_rowlist[off + m] : 0;
        else        tok = (m < cnt) ? m : 0;
        aptr[l] = x + (size_t)tok * ND + kA[l];
    }
    // B-tile loader: one float4 per thread per matrix
    int kB = tid >> 4, nB = (tid & 15) << 2;
    const float* bgp = wg + (size_t)kB * IDIM + n0 + nB;
    const float* bup = wu + (size_t)kB * IDIM + n0 + nB;

    float accg[8][4], accu[8][4];
    #pragma unroll
    for (int r = 0; r < 8; r++)
        #pragma unroll
        for (int c = 0; c < 4; c++) { accg[r][c] = 0.f; accu[r][c] = 0.f; }

    float4 ra0 = *(const float4*)(aptr[0]);
    float4 ra1 = *(const float4*)(aptr[1]);
    float4 rbg = *(const float4*)(bgp);
    float4 rbu = *(const float4*)(bup);

    for (int kt = 0; kt < ND; kt += 16) {
        As[kA[0]+0][mA[0]] = ra0.x; As[kA[0]+1][mA[0]] = ra0.y;
        As[kA[0]+2][mA[0]] = ra0.z; As[kA[0]+3][mA[0]] = ra0.w;
        As[kA[1]+0][mA[1]] = ra1.x; As[kA[1]+1][mA[1]] = ra1.y;
        As[kA[1]+2][mA[1]] = ra1.z; As[kA[1]+3][mA[1]] = ra1.w;
        *(float4*)&Bg[kB][nB] = rbg;
        *(float4*)&Bu[kB][nB] = rbu;
        __syncthreads();
        if (kt + 16 < ND) {
            ra0 = *(const float4*)(aptr[0] + kt + 16);
            ra1 = *(const float4*)(aptr[1] + kt + 16);
            rbg = *(const float4*)(bgp + (size_t)(kt + 16) * IDIM);
            rbu = *(const float4*)(bup + (size_t)(kt + 16) * IDIM);
        }
        #pragma unroll
        for (int kk = 0; kk < 16; kk++) {
            float a[8];
            *(float4*)&a[0] = *(const float4*)&As[kk][ty * 8];
            *(float4*)&a[4] = *(const float4*)&As[kk][ty * 8 + 4];
            float4 b0 = *(const float4*)&Bg[kk][tx * 4];
            float4 b1 = *(const float4*)&Bu[kk][tx * 4];
            float bg4[4] = {b0.x, b0.y, b0.z, b0.w};
            float bu4[4] = {b1.x, b1.y, b1.z, b1.w};
            #pragma unroll
            for (int r = 0; r < 8; r++)
                #pragma unroll
                for (int c = 0; c < 4; c++) {
                    accg[r][c] = fmaf(a[r], bg4[c], accg[r][c]);
                    accu[r][c] = fmaf(a[r], bu4[c], accu[r][c]);
                }
        }
        __syncthreads();
    }
    // epilogue: silu(gate) * up
    #pragma unroll
    for (int r = 0; r < 8; r++) {
        int m = m0 + ty * 8 + r;
        if (m >= cnt) continue;
        float* hp = H + (size_t)(off + m) * IDIM + n0 + tx * 4;
        float4 hv;
        {
            float g0 = accg[r][0], g1 = accg[r][1], g2 = accg[r][2], g3 = accg[r][3];
            hv.x = g0 / (1.f + expf(-g0)) * accu[r][0];
            hv.y = g1 / (1.f + expf(-g1)) * accu[r][1];
            hv.z = g2 / (1.f + expf(-g2)) * accu[r][2];
            hv.w = g3 / (1.f + expf(-g3)) * accu[r][3];
        }
        *(float4*)hp = hv;
    }
}

// ---------------- GEMM 2: out (+)= H @ Wd  ----------------
template<int IDIM, bool ROUTED>
__global__ void __launch_bounds__(256, 2)
gemm_down(const float* __restrict__ Wd,
          float* __restrict__ out) {
    int e   = ROUTED ? blockIdx.z : 0;
    int cnt = ROUTED ? g_counts[e]  : NT;
    int off = ROUTED ? g_offsets[e] : 0;
    int m0  = blockIdx.x * 128;
    if (m0 >= cnt) return;
    int n0  = blockIdx.y * 64;
    const float* wd = Wd + (size_t)e * IDIM * ND;
    const float* H  = ROUTED ? g_h : g_hs;

    __shared__ float As[16][132];
    __shared__ float Bs[16][68];

    int tid = threadIdx.x;
    int tx = tid & 15, ty = tid >> 4;

    const float* aptr[2];
    int mA[2], kA[2];
    #pragma unroll
    for (int l = 0; l < 2; l++) {
        int idx = tid + l * 256;
        mA[l] = idx >> 2; kA[l] = (idx & 3) << 2;
        int m = m0 + mA[l];
        int hr = (m < cnt) ? (off + m) : off;  // clamp to valid row (result discarded)
        aptr[l] = H + (size_t)hr * IDIM + kA[l];
    }
    int kB = tid >> 4, nB = (tid & 15) << 2;
    const float* bp = wd + (size_t)kB * ND + n0 + nB;

    float acc[8][4];
    #pragma unroll
    for (int r = 0; r < 8; r++)
        #pragma unroll
        for (int c = 0; c < 4; c++) acc[r][c] = 0.f;

    float4 ra0 = *(const float4*)(aptr[0]);
    float4 ra1 = *(const float4*)(aptr[1]);
    float4 rb  = *(const float4*)(bp);

    for (int kt = 0; kt < IDIM; kt += 16) {
        As[kA[0]+0][mA[0]] = ra0.x; As[kA[0]+1][mA[0]] = ra0.y;
        As[kA[0]+2][mA[0]] = ra0.z; As[kA[0]+3][mA[0]] = ra0.w;
        As[kA[1]+0][mA[1]] = ra1.x; As[kA[1]+1][mA[1]] = ra1.y;
        As[kA[1]+2][mA[1]] = ra1.z; As[kA[1]+3][mA[1]] = ra1.w;
        *(float4*)&Bs[kB][nB] = rb;
        __syncthreads();
        if (kt + 16 < IDIM) {
            ra0 = *(const float4*)(aptr[0] + kt + 16);
            ra1 = *(const float4*)(aptr[1] + kt + 16);
            rb  = *(const float4*)(bp + (size_t)(kt + 16) * ND);
        }
        #pragma unroll
        for (int kk = 0; kk < 16; kk++) {
            float a[8];
            *(float4*)&a[0] = *(const float4*)&As[kk][ty * 8];
            *(float4*)&a[4] = *(const float4*)&As[kk][ty * 8 + 4];
            float4 b0 = *(const float4*)&Bs[kk][tx * 4];
            float b4[4] = {b0.x, b0.y, b0.z, b0.w};
            #pragma unroll
            for (int r = 0; r < 8; r++)
                #pragma unroll
                for (int c = 0; c < 4; c++)
                    acc[r][c] = fmaf(a[r], b4[c], acc[r][c]);
        }
        __syncthreads();
    }
    #pragma unroll
    for (int r = 0; r < 8; r++) {
        int m = m0 + ty * 8 + r;
        if (m >= cnt) continue;
        if (ROUTED) {
            int gr = off + m;
            int t  = g_rowlist[gr];
            float w = g_roww[gr] * 2.5f;   // routed scaling
            float* op = out + (size_t)t * ND + n0 + tx * 4;
            #pragma unroll
            for (int c = 0; c < 4; c++) atomicAdd(&op[c], w * acc[r][c]);
        } else {
            float* op = out + (size_t)m * ND + n0 + tx * 4;
            float4 v; v.x = acc[r][0]; v.y = acc[r][1]; v.z = acc[r][2]; v.w = acc[r][3];
            *(float4*)op = v;
        }
    }
}

// ---------------- launch ----------------
extern "C" void kernel_launch(void* const* d_in, const int* in_sizes, int n_in,
                              void* d_out, int out_size) {
    const float* x       = (const float*)d_in[0];
    const float* gate_w  = (const float*)d_in[1];
    const float* gate_b  = (const float*)d_in[2];
    const float* w_gate  = (const float*)d_in[3];
    const float* w_up    = (const float*)d_in[4];
    const float* w_down  = (const float*)d_in[5];
    const float* sw_gate = (const float*)d_in[6];
    const float* sw_up   = (const float*)d_in[7];
    const float* sw_down = (const float*)d_in[8];
    float* out = (float*)d_out;

    zero_kernel   <<<1, 32>>>();
    gate_kernel   <<<NT, 256>>>(x, gate_w, gate_b);
    scan_kernel   <<<1, 32>>>();
    scatter_kernel<<<NA / 256, 256>>>();

    // shared expert: gate/up then down (down WRITES out -> must precede routed atomics)
    gemm_gated<NSI, false><<<dim3(NT / 128, NSI / 64, 1), 256>>>(x, sw_gate, sw_up);
    // routed experts: gate/up (independent of shared, same stream keeps order)
    gemm_gated<NI,  true ><<<dim3(NT / 128, NI  / 64, NE), 256>>>(x, w_gate, w_up);
    // shared down-proj: plain stores initialize out
    gemm_down<NSI, false><<<dim3(NT / 128, ND / 64, 1), 256>>>(sw_down, out);
    // routed down-proj: weighted atomic accumulation into out
    gemm_down<NI,  true ><<<dim3(NT / 128, ND / 64, NE), 256>>>(w_down, out);
}